// round 13
// baseline (speedup 1.0000x reference)
#include <cuda_runtime.h>
#include <cuda_bf16.h>
#include <cstdint>

#define B_ 256
#define T_ 127
#define K_ 128
#define H_ 256
#define G4_ 1024
#define BT_ (B_ * T_)
#define CL_ 8

__device__ float g_gx[(size_t)BT_ * G4_];

__device__ __forceinline__ unsigned su32(const void* p) { return (unsigned)__cvta_generic_to_shared(p); }
__device__ __forceinline__ unsigned mapa_rank(unsigned a, unsigned r) {
    unsigned x; asm("mapa.shared::cluster.u32 %0, %1, %2;" : "=r"(x) : "r"(a), "r"(r)); return x;
}
__device__ __forceinline__ void csync() {
    asm volatile("barrier.cluster.arrive.aligned;" ::: "memory");
    asm volatile("barrier.cluster.wait.aligned;" ::: "memory");
}
__device__ __forceinline__ void mbar_init(unsigned a, unsigned c) {
    asm volatile("mbarrier.init.shared.b64 [%0], %1;" :: "r"(a), "r"(c) : "memory");
}
__device__ __forceinline__ void arr_remote(unsigned ra) {
    asm volatile("mbarrier.arrive.release.cluster.shared::cluster.b64 _, [%0];" :: "r"(ra) : "memory");
}
__device__ __forceinline__ void mwait(unsigned a, unsigned ph) {
    asm volatile("{.reg .pred P;\nLW%=:\n"
                 "mbarrier.try_wait.parity.acquire.cluster.shared::cta.b64 P, [%0], %1, 0x989680;\n"
                 "@P bra.uni LD%=;\nbra.uni LW%=;\nLD%=:\n}" :: "r"(a), "r"(ph) : "memory");
}
__device__ __forceinline__ void st_cl_v4(unsigned ra, uint4 v) {
    asm volatile("st.shared::cluster.v4.b32 [%0], {%1,%2,%3,%4};"
                 :: "r"(ra), "r"(v.x), "r"(v.y), "r"(v.z), "r"(v.w) : "memory");
}
__device__ __forceinline__ float sigm(float x) { return 1.f / (1.f + __expf(-x)); }
__device__ __forceinline__ float ftanh(float x) { return 2.f / (1.f + __expf(-2.f * x)) - 1.f; }

#define MMA(d, A, bb0, bb1) \
    asm volatile("mma.sync.aligned.m16n8k16.row.col.f32.bf16.bf16.f32 " \
                 "{%0,%1,%2,%3},{%4,%5,%6,%7},{%8,%9},{%0,%1,%2,%3};" \
                 : "+f"(d[0]), "+f"(d[1]), "+f"(d[2]), "+f"(d[3]) \
                 : "r"(A[0]), "r"(A[1]), "r"(A[2]), "r"(A[3]), "r"(bb0), "r"(bb1))
#define LDB(bb0, bb1, ad) \
    asm volatile("ldmatrix.sync.aligned.m8n8.x2.trans.shared.b16 {%0,%1}, [%2];" \
                 : "=r"(bb0), "=r"(bb1) : "r"(ad))
#define LDA(A, ad) \
    asm volatile("ldmatrix.sync.aligned.m8n8.x4.shared.b16 {%0,%1,%2,%3}, [%4];" \
                 : "=r"(A[0]), "=r"(A[1]), "=r"(A[2]), "=r"(A[3]) : "r"(ad))

// ---- k_alpha (unchanged, passing) -------------------------------------------
__global__ void __launch_bounds__(512) k_alpha(const float* __restrict__ inp,
                                               const float* __restrict__ fc_w,
                                               float* __restrict__ ow) {
    __shared__ float wx[128], part[4][128], rm[4], rs[4];
    const int tid = threadIdx.x, b = blockIdx.x, k = tid & 127, tq = tid >> 7;
    if (tid < 128) wx[tid] = (tid < T_) ? fc_w[2 * H_ + tid] : 0.f;
    __syncthreads();
    const float* ib = inp + (size_t)b * T_ * K_;
    float acc = 0.f;
    const int t1 = (tq * 32 + 32 < T_) ? tq * 32 + 32 : T_;
    for (int t = tq * 32; t < t1; t++) acc += ib[t * K_ + k] * wx[t];
    part[tq][k] = acc;
    __syncthreads();
    float a = part[0][k] + part[1][k] + part[2][k] + part[3][k];
    float m = a;
#pragma unroll
    for (int o = 16; o; o >>= 1) m = fmaxf(m, __shfl_xor_sync(~0u, m, o));
    rm[(tid >> 5) & 3] = m; __syncthreads();
    m = fmaxf(fmaxf(rm[0], rm[1]), fmaxf(rm[2], rm[3]));
    float e = __expf(a - m), s = e;
#pragma unroll
    for (int o = 16; o; o >>= 1) s += __shfl_xor_sync(~0u, s, o);
    rs[(tid >> 5) & 3] = s; __syncthreads();
    const float al = e / (rs[0] + rs[1] + rs[2] + rs[3]);
    float* ob = ow + (size_t)b * T_ * K_;
    for (int t = tq; t < T_; t += 4) ob[t * K_ + k] = al * ib[t * K_ + k];
}

// ---- k_xgemm (unchanged, passing) -------------------------------------------
#define XGB 201728
__global__ void __launch_bounds__(256, 1) k_xgemm(const float* __restrict__ xw,
                                                  const float* __restrict__ Wih,
                                                  const float* __restrict__ bi,
                                                  const float* __restrict__ bh) {
    extern __shared__ __align__(128) char sx[];
    __nv_bfloat16* sA = (__nv_bfloat16*)sx;
    __nv_bfloat16* sB = (__nv_bfloat16*)(sx + 65536);
    float* bias = (float*)(sx + 200704);
    const int tid = threadIdx.x, w = tid >> 5, lane = tid & 31;
    const int bt0 = (blockIdx.x >> 2) * 128, col0 = (blockIdx.x & 3) * 256;

    for (int i = tid; i < 16384; i += 256) {
        float f = xw[(size_t)(bt0 + (i >> 7)) * K_ + (i & 127)];
        __nv_bfloat16 h = __float2bfloat16(f);
        sA[i] = h;
        sA[16384 + i] = __float2bfloat16(f - __bfloat162float(h));
    }
    for (int i = tid; i < 32768; i += 256) {
        int r = i >> 7, k = i & 127;
        float f = Wih[(size_t)(col0 + r) * K_ + k];
        __nv_bfloat16 h = __float2bfloat16(f);
        sB[k * 264 + r] = h;
        sB[33792 + k * 264 + r] = __float2bfloat16(f - __bfloat162float(h));
    }
    if (tid < 256) bias[tid] = bi[col0 + tid] + bh[col0 + tid];
    __syncthreads();

    unsigned ahi[8][4], alo[8][4];
    const unsigned ao = su32(sx) + (unsigned)((w * 16 + (lane & 15)) * 256 + (lane >> 4) * 16);
#pragma unroll
    for (int kc = 0; kc < 8; kc++) { LDA(ahi[kc], ao + kc * 32); LDA(alo[kc], ao + 32768 + kc * 32); }
    const unsigned bb = su32(sx) + 65536u + (unsigned)((lane & 15) * 528);

#pragma unroll 1
    for (int nc = 0; nc < 32; nc++) {
        float da[4] = {0,0,0,0}, db[4] = {0,0,0,0}, dc[4] = {0,0,0,0};
#pragma unroll
        for (int kc = 0; kc < 8; kc++) {
            unsigned b0, b1, l0, l1;
            LDB(b0, b1, bb + kc * 8448 + nc * 16);
            LDB(l0, l1, bb + 67584 + kc * 8448 + nc * 16);
            MMA(da, ahi[kc], b0, b1);
            MMA(db, alo[kc], b0, b1);
            MMA(dc, ahi[kc], l0, l1);
        }
        const int c = nc * 8 + (lane & 3) * 2, g = lane >> 2;
        float2 b2 = *(float2*)(bias + c);
        float2 o1 = make_float2(da[0] + db[0] + dc[0] + b2.x, da[1] + db[1] + dc[1] + b2.y);
        float2 o2 = make_float2(da[2] + db[2] + dc[2] + b2.x, da[3] + db[3] + dc[3] + b2.y);
        *(float2*)(g_gx + (size_t)(bt0 + w * 16 + g) * G4_ + col0 + c) = o1;
        *(float2*)(g_gx + (size_t)(bt0 + w * 16 + g + 8) * G4_ + col0 + c) = o2;
    }
}

// ---- k_lstm: warp-autonomous step loop ---------------------------------------
// smem: bars@0 (full0@0,full1@8,empty0@16,empty1@24)
// hT@1024: [2 buf][2 hl][256 k][16 n] bf16 (32KB)
// hs@33792: [2 buf][2 hl][32 u][16 m] bf16 (4KB)
// Wst@37888: 128x256 bf16 (64KB, init only) ; total 103424
#define LSMB 103424
__global__ void __launch_bounds__(256, 1) __cluster_dims__(CL_, 1, 1)
k_lstm(const float* __restrict__ W_hh, float* __restrict__ out_h) {
    extern __shared__ __align__(1024) char smc[];
    float* smf = (float*)smc;
    const int tid = threadIdx.x, w = tid >> 5, lane = tid & 31;
    unsigned rank; asm("mov.u32 %0, %%cluster_ctarank;" : "=r"(rank));
    const int b0 = (blockIdx.x / CL_) * 16;
    const unsigned sb = su32(smc);

    if (tid == 0) {
        mbar_init(sb + 0, 8);   mbar_init(sb + 8, 8);    // full[0], full[1]
        mbar_init(sb + 16, 64); mbar_init(sb + 24, 64);  // empty[0], empty[1]
    }
    for (int i = tid; i < 8192; i += 256) smf[256 + i] = 0.f;    // zero hT

    // ---- W A-fragments, permuted: frag row r of warp w -> gate (r>>2), unit w*4+(r&3)
    __nv_bfloat16* Wst = (__nv_bfloat16*)(smc + 37888);
    unsigned ahi[16][4], alo[16][4];
    const unsigned abase = su32(Wst) + (unsigned)((w * 16 + (lane & 15)) * 512 + (lane >> 4) * 16);
    for (int i = tid; i < 32768; i += 256) {
        int fr = i >> 8, k = i & 255;
        int ww = fr >> 4, r = fr & 15;
        int grow = (r >> 2) * 256 + (int)rank * 32 + ww * 4 + (r & 3);
        Wst[fr * 256 + k] = __float2bfloat16(W_hh[grow * H_ + k]);
    }
    __syncthreads();
#pragma unroll
    for (int kc = 0; kc < 16; kc++) LDA(ahi[kc], abase + kc * 32);
    __syncthreads();
    for (int i = tid; i < 32768; i += 256) {
        int fr = i >> 8, k = i & 255;
        int ww = fr >> 4, r = fr & 15;
        int grow = (r >> 2) * 256 + (int)rank * 32 + ww * 4 + (r & 3);
        float wv = W_hh[grow * H_ + k];
        Wst[fr * 256 + k] = __float2bfloat16(wv - __bfloat162float(__float2bfloat16(wv)));
    }
    __syncthreads();
#pragma unroll
    for (int kc = 0; kc < 16; kc++) LDA(alo[kc], abase + kc * 32);
    __syncthreads();

    unsigned rbase[CL_];
#pragma unroll
    for (int pr = 0; pr < CL_; pr++) rbase[pr] = mapa_rank(sb, pr);

    const unsigned hT0 = sb + 1024;
    const unsigned brow = (unsigned)((lane & 15) * 32);

    // cell roles
    const int g = lane >> 2;
    const bool low = g < 4;
    const int u_loc = w * 4 + (g & 3);
    const int uu = (int)rank * 32 + u_loc;
    const int my_m0 = (low ? 0 : 8) + 2 * (lane & 3);
    float cA = 0.f, cB = 0.f;
    const float* gx0 = g_gx + ((size_t)(b0 + my_m0) * T_) * G4_ + uu;
    const float* gx1 = gx0 + (size_t)T_ * G4_;
    float* oA = out_h + (size_t)(b0 + my_m0) * T_ * H_ + uu;
    float* oB = oA + (size_t)T_ * H_;
    // hs store slot: pack (m, m+1) bf16 into one u32
    unsigned* hsHi = (unsigned*)(smc + 33792 + u_loc * 32 + my_m0 * 2);
    // send role: warp w ships 2KB to rank w
    const unsigned ssrc = su32(smc) + 33792u + (unsigned)((lane >> 4) * 1024 + (lane & 15) * 64);
    const unsigned sdst = 1024u + (unsigned)((lane >> 4) * 8192 + (int)rank * 1024 + (lane & 15) * 64);

    csync();

    for (int t = 0; t < T_; t++) {
        const int p = t & 1, q = p ^ 1;
        const unsigned pw = (unsigned)(((t - 1) >> 1) & 1);

        // prefetch gx (8 LDG; consumed after mma)
        float gA[4], gB[4];
        {
            const float* ga = gx0 + (size_t)t * G4_;
            const float* gb = gx1 + (size_t)t * G4_;
#pragma unroll
            for (int j = 0; j < 4; j++) { gA[j] = ga[j * 256]; gB[j] = gb[j * 256]; }
        }

        float d0[4] = {0,0,0,0}, d1[4] = {0,0,0,0};
        if (t > 0) {
            mwait(sb + p * 8, pw);                       // per-warp full[p]
            const unsigned bbh = hT0 + (unsigned)p * 16384 + brow;
            float a0[4] = {0,0,0,0}, e0[4] = {0,0,0,0}, f0[4] = {0,0,0,0};
            float a1[4] = {0,0,0,0}, e1[4] = {0,0,0,0}, f1[4] = {0,0,0,0};
#pragma unroll
            for (int kc = 0; kc < 16; kc++) {
                unsigned bh0, bh1, bl0, bl1, ch0, ch1, cl0, cl1;
                LDB(bh0, bh1, bbh + kc * 512);
                LDB(bl0, bl1, bbh + 8192 + kc * 512);
                LDB(ch0, ch1, bbh + kc * 512 + 16);
                LDB(cl0, cl1, bbh + 8192 + kc * 512 + 16);
                MMA(a0, ahi[kc], bh0, bh1);
                MMA(e0, alo[kc], bh0, bh1);
                MMA(f0, ahi[kc], bl0, bl1);
                MMA(a1, ahi[kc], ch0, ch1);
                MMA(e1, alo[kc], ch0, ch1);
                MMA(f1, ahi[kc], cl0, cl1);
            }
#pragma unroll
            for (int i = 0; i < 4; i++) {
                d0[i] = a0[i] + e0[i] + f0[i];
                d1[i] = a1[i] + e1[i] + f1[i];
            }
        }
        // release empty[p] (per-warp; hT[p] reads complete)
        __syncwarp();
        if (lane == 0) {
#pragma unroll
            for (int pr = 0; pr < CL_; pr++) arr_remote(rbase[pr] + 16 + p * 8);
        }

        // gate exchange: lane L <-> L^16 (blend: low sends d1, high sends d0)
        float rc[4];
#pragma unroll
        for (int j = 0; j < 4; j++) {
            float snd = low ? d1[j] : d0[j];
            rc[j] = __shfl_xor_sync(~0u, snd, 16);
        }
        // low lane: i=d0[0..1], g=d0[2..3], f=rc[0..1], o=rc[2..3]  (batches half0)
        // high lane: i=rc[0..1], g=rc[2..3], f=d1[0..1], o=d1[2..3] (batches half1)
        float i0 = (low ? d0[0] : rc[0]) + gA[0];
        float i1 = (low ? d0[1] : rc[1]) + gB[0];
        float f0v = (low ? rc[0] : d1[0]) + gA[1];
        float f1v = (low ? rc[1] : d1[1]) + gB[1];
        float G0 = (low ? d0[2] : rc[2]) + gA[2];
        float G1 = (low ? d0[3] : rc[3]) + gB[2];
        float o0 = (low ? rc[2] : d1[2]) + gA[3];
        float o1 = (low ? rc[3] : d1[3]) + gB[3];

        cA = sigm(f0v) * cA + sigm(i0) * ftanh(G0);
        float hA = sigm(o0) * ftanh(cA);
        cB = sigm(f1v) * cB + sigm(i1) * ftanh(G1);
        float hB = sigm(o1) * ftanh(cB);

        oA[(size_t)t * H_] = hA;
        oB[(size_t)t * H_] = hB;

        if (t < T_ - 1) {
            // stage h (hi/lo planes), packed 2 batches per u32
            __nv_bfloat16 hiA = __float2bfloat16(hA), hiB = __float2bfloat16(hB);
            __nv_bfloat16 loA = __float2bfloat16(hA - __bfloat162float(hiA));
            __nv_bfloat16 loB = __float2bfloat16(hB - __bfloat162float(hiB));
            unsigned pk_hi = (unsigned)*(unsigned short*)&hiA | ((unsigned)*(unsigned short*)&hiB << 16);
            unsigned pk_lo = (unsigned)*(unsigned short*)&loA | ((unsigned)*(unsigned short*)&loB << 16);
            unsigned* slot = (unsigned*)((char*)hsHi + q * 2048);
            slot[0] = pk_hi;
            slot[256] = pk_lo;          // +1024 bytes (lo plane)
            __syncthreads();            // hs[q] complete (the ONLY block sync)
            if (t > 0) mwait(sb + 16 + q * 8, pw);       // per-warp empty[q]
            {
                const unsigned s0 = ssrc + (unsigned)q * 2048;
                const unsigned d0a = sdst + (unsigned)q * 16384;
                uint4 v0 = *(const uint4*)(smc + (s0 - sb));
                uint4 v1 = *(const uint4*)(smc + (s0 - sb) + 16);
                uint4 v2 = *(const uint4*)(smc + (s0 - sb) + 32);
                uint4 v3 = *(const uint4*)(smc + (s0 - sb) + 48);
                st_cl_v4(rbase[w] + d0a, v0);
                st_cl_v4(rbase[w] + d0a + 16, v1);
                st_cl_v4(rbase[w] + d0a + 32, v2);
                st_cl_v4(rbase[w] + d0a + 48, v3);
            }
            __syncwarp();
            if (lane == 0) arr_remote(rbase[w] + q * 8);   // full[q] (count 8)
        }
    }
    csync();
}

// ---- launch -------------------------------------------------------------------
extern "C" void kernel_launch(void* const* d_in, const int* in_sizes, int n_in,
                              void* d_out, int out_size) {
    const float* input = (const float*)d_in[0];
    const float* W_ih  = (const float*)d_in[1];
    const float* W_hh  = (const float*)d_in[2];
    const float* b_ih  = (const float*)d_in[3];
    const float* b_hh  = (const float*)d_in[4];
    const float* fc_w  = (const float*)d_in[5];
    float* out   = (float*)d_out;
    float* out_w = out;
    float* out_h = out + (size_t)B_ * T_ * K_;

    cudaFuncSetAttribute(k_xgemm, cudaFuncAttributeMaxDynamicSharedMemorySize, XGB);
    cudaFuncSetAttribute(k_lstm,  cudaFuncAttributeMaxDynamicSharedMemorySize, LSMB);

    k_alpha<<<B_, 512>>>(input, fc_w, out_w);
    k_xgemm<<<(BT_ / 128) * 4, 256, XGB>>>(out_w, W_ih, b_ih, b_hh);
    k_lstm<<<(B_ / 16) * CL_, 256, LSMB>>>(W_hh, out_h);
}

// round 14
// speedup vs baseline: 1.8607x; 1.8607x over previous
#include <cuda_runtime.h>
#include <cuda_bf16.h>
#include <cuda_fp16.h>
#include <cstdint>

#define B_ 256
#define T_ 127
#define K_ 128
#define H_ 256
#define G4_ 1024
#define BT_ (B_ * T_)
#define CL_ 8

__device__ float g_gx[(size_t)BT_ * G4_];

__device__ __forceinline__ unsigned su32(const void* p) { return (unsigned)__cvta_generic_to_shared(p); }
__device__ __forceinline__ unsigned mapa_rank(unsigned a, unsigned r) {
    unsigned x; asm("mapa.shared::cluster.u32 %0, %1, %2;" : "=r"(x) : "r"(a), "r"(r)); return x;
}
__device__ __forceinline__ void csync() {
    asm volatile("barrier.cluster.arrive.aligned;" ::: "memory");
    asm volatile("barrier.cluster.wait.aligned;" ::: "memory");
}
__device__ __forceinline__ void mbar_init(unsigned a, unsigned c) {
    asm volatile("mbarrier.init.shared.b64 [%0], %1;" :: "r"(a), "r"(c) : "memory");
}
__device__ __forceinline__ void arr_remote(unsigned ra) {
    asm volatile("mbarrier.arrive.release.cluster.shared::cluster.b64 _, [%0];" :: "r"(ra) : "memory");
}
__device__ __forceinline__ void mwait(unsigned a, unsigned ph) {
    asm volatile("{.reg .pred P;\nLW%=:\n"
                 "mbarrier.try_wait.parity.acquire.cluster.shared::cta.b64 P, [%0], %1, 0x989680;\n"
                 "@P bra.uni LD%=;\nbra.uni LW%=;\nLD%=:\n}" :: "r"(a), "r"(ph) : "memory");
}
__device__ __forceinline__ void st_cl_v4(unsigned ra, uint4 v) {
    asm volatile("st.shared::cluster.v4.b32 [%0], {%1,%2,%3,%4};"
                 :: "r"(ra), "r"(v.x), "r"(v.y), "r"(v.z), "r"(v.w) : "memory");
}
__device__ __forceinline__ float sigm(float x) { return 1.f / (1.f + __expf(-x)); }
__device__ __forceinline__ float ftanh(float x) { return 2.f / (1.f + __expf(-2.f * x)) - 1.f; }

#define MMAB(d, A, bb0, bb1) \
    asm volatile("mma.sync.aligned.m16n8k16.row.col.f32.bf16.bf16.f32 " \
                 "{%0,%1,%2,%3},{%4,%5,%6,%7},{%8,%9},{%0,%1,%2,%3};" \
                 : "+f"(d[0]), "+f"(d[1]), "+f"(d[2]), "+f"(d[3]) \
                 : "r"(A[0]), "r"(A[1]), "r"(A[2]), "r"(A[3]), "r"(bb0), "r"(bb1))
#define MMAH(d, A, bb0, bb1) \
    asm volatile("mma.sync.aligned.m16n8k16.row.col.f32.f16.f16.f32 " \
                 "{%0,%1,%2,%3},{%4,%5,%6,%7},{%8,%9},{%0,%1,%2,%3};" \
                 : "+f"(d[0]), "+f"(d[1]), "+f"(d[2]), "+f"(d[3]) \
                 : "r"(A[0]), "r"(A[1]), "r"(A[2]), "r"(A[3]), "r"(bb0), "r"(bb1))
#define LDB(bb0, bb1, ad) \
    asm volatile("ldmatrix.sync.aligned.m8n8.x2.trans.shared.b16 {%0,%1}, [%2];" \
                 : "=r"(bb0), "=r"(bb1) : "r"(ad))
#define LDA(A, ad) \
    asm volatile("ldmatrix.sync.aligned.m8n8.x4.shared.b16 {%0,%1,%2,%3}, [%4];" \
                 : "=r"(A[0]), "=r"(A[1]), "=r"(A[2]), "=r"(A[3]) : "r"(ad))

// ---- k_alpha (unchanged, passing) -------------------------------------------
__global__ void __launch_bounds__(512) k_alpha(const float* __restrict__ inp,
                                               const float* __restrict__ fc_w,
                                               float* __restrict__ ow) {
    __shared__ float wx[128], part[4][128], rm[4], rs[4];
    const int tid = threadIdx.x, b = blockIdx.x, k = tid & 127, tq = tid >> 7;
    if (tid < 128) wx[tid] = (tid < T_) ? fc_w[2 * H_ + tid] : 0.f;
    __syncthreads();
    const float* ib = inp + (size_t)b * T_ * K_;
    float acc = 0.f;
    const int t1 = (tq * 32 + 32 < T_) ? tq * 32 + 32 : T_;
    for (int t = tq * 32; t < t1; t++) acc += ib[t * K_ + k] * wx[t];
    part[tq][k] = acc;
    __syncthreads();
    float a = part[0][k] + part[1][k] + part[2][k] + part[3][k];
    float m = a;
#pragma unroll
    for (int o = 16; o; o >>= 1) m = fmaxf(m, __shfl_xor_sync(~0u, m, o));
    rm[(tid >> 5) & 3] = m; __syncthreads();
    m = fmaxf(fmaxf(rm[0], rm[1]), fmaxf(rm[2], rm[3]));
    float e = __expf(a - m), s = e;
#pragma unroll
    for (int o = 16; o; o >>= 1) s += __shfl_xor_sync(~0u, s, o);
    rs[(tid >> 5) & 3] = s; __syncthreads();
    const float al = e / (rs[0] + rs[1] + rs[2] + rs[3]);
    float* ob = ow + (size_t)b * T_ * K_;
    for (int t = tq; t < T_; t += 4) ob[t * K_ + k] = al * ib[t * K_ + k];
}

// ---- k_xgemm (unchanged, passing) -------------------------------------------
#define XGB 201728
__global__ void __launch_bounds__(256, 1) k_xgemm(const float* __restrict__ xw,
                                                  const float* __restrict__ Wih,
                                                  const float* __restrict__ bi,
                                                  const float* __restrict__ bh) {
    extern __shared__ __align__(128) char sx[];
    __nv_bfloat16* sA = (__nv_bfloat16*)sx;
    __nv_bfloat16* sB = (__nv_bfloat16*)(sx + 65536);
    float* bias = (float*)(sx + 200704);
    const int tid = threadIdx.x, w = tid >> 5, lane = tid & 31;
    const int bt0 = (blockIdx.x >> 2) * 128, col0 = (blockIdx.x & 3) * 256;

    for (int i = tid; i < 16384; i += 256) {
        float f = xw[(size_t)(bt0 + (i >> 7)) * K_ + (i & 127)];
        __nv_bfloat16 h = __float2bfloat16(f);
        sA[i] = h;
        sA[16384 + i] = __float2bfloat16(f - __bfloat162float(h));
    }
    for (int i = tid; i < 32768; i += 256) {
        int r = i >> 7, k = i & 127;
        float f = Wih[(size_t)(col0 + r) * K_ + k];
        __nv_bfloat16 h = __float2bfloat16(f);
        sB[k * 264 + r] = h;
        sB[33792 + k * 264 + r] = __float2bfloat16(f - __bfloat162float(h));
    }
    if (tid < 256) bias[tid] = bi[col0 + tid] + bh[col0 + tid];
    __syncthreads();

    unsigned ahi[8][4], alo[8][4];
    const unsigned ao = su32(sx) + (unsigned)((w * 16 + (lane & 15)) * 256 + (lane >> 4) * 16);
#pragma unroll
    for (int kc = 0; kc < 8; kc++) { LDA(ahi[kc], ao + kc * 32); LDA(alo[kc], ao + 32768 + kc * 32); }
    const unsigned bb = su32(sx) + 65536u + (unsigned)((lane & 15) * 528);

#pragma unroll 1
    for (int nc = 0; nc < 32; nc++) {
        float da[4] = {0,0,0,0}, db[4] = {0,0,0,0}, dc[4] = {0,0,0,0};
#pragma unroll
        for (int kc = 0; kc < 8; kc++) {
            unsigned b0, b1, l0, l1;
            LDB(b0, b1, bb + kc * 8448 + nc * 16);
            LDB(l0, l1, bb + 67584 + kc * 8448 + nc * 16);
            MMAB(da, ahi[kc], b0, b1);
            MMAB(db, alo[kc], b0, b1);
            MMAB(dc, ahi[kc], l0, l1);
        }
        const int c = nc * 8 + (lane & 3) * 2, g = lane >> 2;
        float2 b2 = *(float2*)(bias + c);
        float2 o1 = make_float2(da[0] + db[0] + dc[0] + b2.x, da[1] + db[1] + dc[1] + b2.y);
        float2 o2 = make_float2(da[2] + db[2] + dc[2] + b2.x, da[3] + db[3] + dc[3] + b2.y);
        *(float2*)(g_gx + (size_t)(bt0 + w * 16 + g) * G4_ + col0 + c) = o1;
        *(float2*)(g_gx + (size_t)(bt0 + w * 16 + g + 8) * G4_ + col0 + c) = o2;
    }
}

// ---- k_lstm: R11 structure, fp16 2-term MMA ----------------------------------
// smem: bars@0; hT@1024 [2 buf][256 k][16 n] fp16 (16KB);
// gt@17408 [128][18]f (9216B); hs@26624 [2 buf][32 u][16 m] fp16 (2KB);
// Wst@28672 128x256 fp16 (64KB, init only); total 94208
#define LSMB 94208
__global__ void __launch_bounds__(256, 1) __cluster_dims__(CL_, 1, 1)
k_lstm(const float* __restrict__ W_hh, float* __restrict__ out_h) {
    extern __shared__ __align__(1024) char smc[];
    float* smf = (float*)smc;
    const int tid = threadIdx.x, wid = tid >> 5, lane = tid & 31;
    unsigned rank; asm("mov.u32 %0, %%cluster_ctarank;" : "=r"(rank));
    const int b0 = (blockIdx.x / CL_) * 16;
    const unsigned sb = su32(smc);

    if (tid == 0) {
        mbar_init(sb + 0, 8);  mbar_init(sb + 8, 8);    // full[0], full[1]
        mbar_init(sb + 16, 8); mbar_init(sb + 24, 8);   // empty[0], empty[1]
    }
    for (int i = tid; i < 4096; i += 256) smf[256 + i] = 0.f;   // zero hT (16KB)

    // W A-fragments: hi fp16 then lo fp16 (exact pair decomposition)
    __half* Wst = (__half*)(smc + 28672);
    unsigned ahi[16][4], alo[16][4];
    const unsigned abase = su32(Wst) + (unsigned)((wid * 16 + (lane & 15)) * 512 + (lane >> 4) * 16);
    for (int i = tid; i < 32768; i += 256) {
        int r = i >> 8, k = i & 255;
        int grow = (r >> 5) * H_ + (int)rank * 32 + (r & 31);
        Wst[r * 256 + k] = __float2half(W_hh[grow * H_ + k]);
    }
    __syncthreads();
#pragma unroll
    for (int kc = 0; kc < 16; kc++) LDA(ahi[kc], abase + kc * 32);
    __syncthreads();
    for (int i = tid; i < 32768; i += 256) {
        int r = i >> 8, k = i & 255;
        int grow = (r >> 5) * H_ + (int)rank * 32 + (r & 31);
        float w = W_hh[grow * H_ + k];
        Wst[r * 256 + k] = __float2half(w - __half2float(__float2half(w)));
    }
    __syncthreads();
#pragma unroll
    for (int kc = 0; kc < 16; kc++) LDA(alo[kc], abase + kc * 32);
    __syncthreads();

    unsigned rbase[CL_];
#pragma unroll
    for (int pr = 0; pr < CL_; pr++) rbase[pr] = mapa_rank(sb, pr);

    const unsigned hT0 = sb + 1024;                       // buf stride 8192 B
    const unsigned brow = (unsigned)((lane & 15) * 32);

    const int jl = tid & 31, m0 = tid >> 5;
    float c0 = 0.f, c1 = 0.f;
    float* gt = (float*)(smc + 17408);
    __half* hs = (__half*)(smc + 26624);                  // [2][512] fp16
    float* o0 = out_h + (size_t)(b0 + m0) * T_ * H_ + (int)rank * 32 + jl;
    float* o1 = out_h + (size_t)(b0 + m0 + 8) * T_ * H_ + (int)rank * 32 + jl;
    const float* gxb = g_gx + (size_t)b0 * T_ * G4_ + (int)rank * 32 + jl;

    // writer roles: 64 chunks of 16B cover our 1KB slice; 4 groups x 2 ranks
    const int wck = tid & 63;
    const int rg = (tid >> 6) * 2;
    const uint4* wsrc = (const uint4*)(smc + 26624 + wck * 16);
    const unsigned wdst = (unsigned)(1024 + (int)rank * 1024 + wck * 16);

    csync();

    for (int t = 0; t < T_; t++) {
        const int p = t & 1;
        const unsigned pw = (unsigned)(((t - 1) >> 1) & 1);

        const float* gp = gxb + (size_t)t * G4_;
        float gx[8];
#pragma unroll
        for (int q = 0; q < 4; q++) {
            gx[q]     = gp[(size_t)m0 * T_ * G4_ + q * 256];
            gx[4 + q] = gp[(size_t)(m0 + 8) * T_ * G4_ + q * 256];
        }

        float d0[4] = {0.f, 0.f, 0.f, 0.f}, d1[4] = {0.f, 0.f, 0.f, 0.f};
        if (t > 0) {
            if (wid == 0) mwait(sb + p * 8, pw);         // full[p]
            __syncthreads();
            const unsigned bbh = hT0 + (unsigned)p * 8192 + brow;
            float a0[4] = {0,0,0,0}, e0[4] = {0,0,0,0};
            float a1[4] = {0,0,0,0}, e1[4] = {0,0,0,0};
#pragma unroll
            for (int kc = 0; kc < 16; kc++) {
                unsigned bh0, bh1, ch0, ch1;
                LDB(bh0, bh1, bbh + kc * 512);
                LDB(ch0, ch1, bbh + kc * 512 + 16);
                MMAH(a0, ahi[kc], bh0, bh1);
                MMAH(e0, alo[kc], bh0, bh1);
                MMAH(a1, ahi[kc], ch0, ch1);
                MMAH(e1, alo[kc], ch0, ch1);
            }
#pragma unroll
            for (int i = 0; i < 4; i++) { d0[i] = a0[i] + e0[i]; d1[i] = a1[i] + e1[i]; }
        }
        {
            int g = lane >> 2, tt = (lane & 3) * 2;
            float* r0 = gt + (wid * 16 + g) * 18;
            float* r1 = r0 + 8 * 18;
            *(float2*)(r0 + tt) = make_float2(d0[0], d0[1]);
            *(float2*)(r1 + tt) = make_float2(d0[2], d0[3]);
            *(float2*)(r0 + 8 + tt) = make_float2(d1[0], d1[1]);
            *(float2*)(r1 + 8 + tt) = make_float2(d1[2], d1[3]);
        }
        __syncthreads();
        if (tid < 8) arr_remote(rbase[tid] + 16 + p * 8);   // release empty[p]

        float gi = gt[jl * 18 + m0] + gx[0];
        float gf = gt[(32 + jl) * 18 + m0] + gx[1];
        float gg = gt[(64 + jl) * 18 + m0] + gx[2];
        float go = gt[(96 + jl) * 18 + m0] + gx[3];
        c0 = sigm(gf) * c0 + sigm(gi) * ftanh(gg);
        float h0 = sigm(go) * ftanh(c0);
        gi = gt[jl * 18 + m0 + 8] + gx[4];
        gf = gt[(32 + jl) * 18 + m0 + 8] + gx[5];
        gg = gt[(64 + jl) * 18 + m0 + 8] + gx[6];
        go = gt[(96 + jl) * 18 + m0 + 8] + gx[7];
        c1 = sigm(gf) * c1 + sigm(gi) * ftanh(gg);
        float h1 = sigm(go) * ftanh(c1);

        o0[(size_t)t * H_] = h0;
        o1[(size_t)t * H_] = h1;

        if (t < T_ - 1) {
            const int q = p ^ 1;
            __half* hq = hs + q * 512;
            hq[jl * 16 + m0] = __float2half(h0);
            hq[jl * 16 + m0 + 8] = __float2half(h1);
            if (wid == 0 && t > 0) mwait(sb + 16 + q * 8, pw);   // empty[q]
            __syncthreads();
            uint4 v = *(const uint4*)((const char*)wsrc + q * 1024);
            unsigned drel = wdst + (unsigned)(q * 8192);
            st_cl_v4(rbase[rg] + drel, v);
            st_cl_v4(rbase[rg + 1] + drel, v);
            __syncthreads();
            if (tid < 8) arr_remote(rbase[tid] + q * 8);   // full[q] release
        }
    }
    csync();
}

// ---- launch -------------------------------------------------------------------
extern "C" void kernel_launch(void* const* d_in, const int* in_sizes, int n_in,
                              void* d_out, int out_size) {
    const float* input = (const float*)d_in[0];
    const float* W_ih  = (const float*)d_in[1];
    const float* W_hh  = (const float*)d_in[2];
    const float* b_ih  = (const float*)d_in[3];
    const float* b_hh  = (const float*)d_in[4];
    const float* fc_w  = (const float*)d_in[5];
    float* out   = (float*)d_out;
    float* out_w = out;
    float* out_h = out + (size_t)B_ * T_ * K_;

    cudaFuncSetAttribute(k_xgemm, cudaFuncAttributeMaxDynamicSharedMemorySize, XGB);
    cudaFuncSetAttribute(k_lstm,  cudaFuncAttributeMaxDynamicSharedMemorySize, LSMB);

    k_alpha<<<B_, 512>>>(input, fc_w, out_w);
    k_xgemm<<<(BT_ / 128) * 4, 256, XGB>>>(out_w, W_ih, b_ih, b_hh);
    k_lstm<<<(B_ / 16) * CL_, 256, LSMB>>>(W_hh, out_h);
}

// round 15
// speedup vs baseline: 1.9617x; 1.0543x over previous
#include <cuda_runtime.h>
#include <cuda_bf16.h>
#include <cuda_fp16.h>
#include <cstdint>

#define B_ 256
#define T_ 127
#define K_ 128
#define H_ 256
#define G4_ 1024
#define BT_ (B_ * T_)
#define CL_ 8

__device__ float g_gx[(size_t)BT_ * G4_];

__device__ __forceinline__ unsigned su32(const void* p) { return (unsigned)__cvta_generic_to_shared(p); }
__device__ __forceinline__ unsigned mapa_rank(unsigned a, unsigned r) {
    unsigned x; asm("mapa.shared::cluster.u32 %0, %1, %2;" : "=r"(x) : "r"(a), "r"(r)); return x;
}
__device__ __forceinline__ void csync() {
    asm volatile("barrier.cluster.arrive.aligned;" ::: "memory");
    asm volatile("barrier.cluster.wait.aligned;" ::: "memory");
}
__device__ __forceinline__ void mbar_init(unsigned a, unsigned c) {
    asm volatile("mbarrier.init.shared.b64 [%0], %1;" :: "r"(a), "r"(c) : "memory");
}
__device__ __forceinline__ void arr_remote(unsigned ra) {
    asm volatile("mbarrier.arrive.release.cluster.shared::cluster.b64 _, [%0];" :: "r"(ra) : "memory");
}
__device__ __forceinline__ void mwait(unsigned a, unsigned ph) {
    asm volatile("{.reg .pred P;\nLW%=:\n"
                 "mbarrier.try_wait.parity.acquire.cluster.shared::cta.b64 P, [%0], %1, 0x989680;\n"
                 "@P bra.uni LD%=;\nbra.uni LW%=;\nLD%=:\n}" :: "r"(a), "r"(ph) : "memory");
}
__device__ __forceinline__ void st_cl_v4(unsigned ra, uint4 v) {
    asm volatile("st.shared::cluster.v4.b32 [%0], {%1,%2,%3,%4};"
                 :: "r"(ra), "r"(v.x), "r"(v.y), "r"(v.z), "r"(v.w) : "memory");
}
__device__ __forceinline__ float sigm(float x) { return 1.f / (1.f + __expf(-x)); }
__device__ __forceinline__ float ftanh(float x) { return 2.f / (1.f + __expf(-2.f * x)) - 1.f; }

#define MMAH(d, A, bb0, bb1) \
    asm volatile("mma.sync.aligned.m16n8k16.row.col.f32.f16.f16.f32 " \
                 "{%0,%1,%2,%3},{%4,%5,%6,%7},{%8,%9},{%0,%1,%2,%3};" \
                 : "+f"(d[0]), "+f"(d[1]), "+f"(d[2]), "+f"(d[3]) \
                 : "r"(A[0]), "r"(A[1]), "r"(A[2]), "r"(A[3]), "r"(bb0), "r"(bb1))
#define LDB(bb0, bb1, ad) \
    asm volatile("ldmatrix.sync.aligned.m8n8.x2.trans.shared.b16 {%0,%1}, [%2];" \
                 : "=r"(bb0), "=r"(bb1) : "r"(ad))
#define LDA(A, ad) \
    asm volatile("ldmatrix.sync.aligned.m8n8.x4.shared.b16 {%0,%1,%2,%3}, [%4];" \
                 : "=r"(A[0]), "=r"(A[1]), "=r"(A[2]), "=r"(A[3]) : "r"(ad))

// ---- k_alpha (unchanged, passing) -------------------------------------------
__global__ void __launch_bounds__(512) k_alpha(const float* __restrict__ inp,
                                               const float* __restrict__ fc_w,
                                               float* __restrict__ ow) {
    __shared__ float wx[128], part[4][128], rm[4], rs[4];
    const int tid = threadIdx.x, b = blockIdx.x, k = tid & 127, tq = tid >> 7;
    if (tid < 128) wx[tid] = (tid < T_) ? fc_w[2 * H_ + tid] : 0.f;
    __syncthreads();
    const float* ib = inp + (size_t)b * T_ * K_;
    float acc = 0.f;
    const int t1 = (tq * 32 + 32 < T_) ? tq * 32 + 32 : T_;
    for (int t = tq * 32; t < t1; t++) acc += ib[t * K_ + k] * wx[t];
    part[tq][k] = acc;
    __syncthreads();
    float a = part[0][k] + part[1][k] + part[2][k] + part[3][k];
    float m = a;
#pragma unroll
    for (int o = 16; o; o >>= 1) m = fmaxf(m, __shfl_xor_sync(~0u, m, o));
    rm[(tid >> 5) & 3] = m; __syncthreads();
    m = fmaxf(fmaxf(rm[0], rm[1]), fmaxf(rm[2], rm[3]));
    float e = __expf(a - m), s = e;
#pragma unroll
    for (int o = 16; o; o >>= 1) s += __shfl_xor_sync(~0u, s, o);
    rs[(tid >> 5) & 3] = s; __syncthreads();
    const float al = e / (rs[0] + rs[1] + rs[2] + rs[3]);
    float* ob = ow + (size_t)b * T_ * K_;
    for (int t = tq; t < T_; t += 4) ob[t * K_ + k] = al * ib[t * K_ + k];
}

// ---- k_xgemm (fp16 2-term): g_gx = xw @ W_ih^T + bias ------------------------
// sAhi@0, sAlo@32768 (128bt x 128k fp16); sB@65536 [128k][264] fp16 (67584B)
// bias@133120 (256 f); total 134144
#define XGB 134144
__global__ void __launch_bounds__(256, 1) k_xgemm(const float* __restrict__ xw,
                                                  const float* __restrict__ Wih,
                                                  const float* __restrict__ bi,
                                                  const float* __restrict__ bh) {
    extern __shared__ __align__(128) char sx[];
    __half* sA = (__half*)sx;
    __half* sB = (__half*)(sx + 65536);
    float* bias = (float*)(sx + 133120);
    const int tid = threadIdx.x, w = tid >> 5, lane = tid & 31;
    const int bt0 = (blockIdx.x >> 2) * 128, col0 = (blockIdx.x & 3) * 256;

    for (int i = tid; i < 16384; i += 256) {
        float f = xw[(size_t)(bt0 + (i >> 7)) * K_ + (i & 127)];
        __half h = __float2half(f);
        sA[i] = h;
        sA[16384 + i] = __float2half(f - __half2float(h));
    }
    for (int i = tid; i < 32768; i += 256) {
        int r = i >> 7, k = i & 127;
        sB[k * 264 + r] = __float2half(Wih[(size_t)(col0 + r) * K_ + k]);
    }
    if (tid < 256) bias[tid] = bi[col0 + tid] + bh[col0 + tid];
    __syncthreads();

    unsigned ahi[8][4], alo[8][4];
    const unsigned ao = su32(sx) + (unsigned)((w * 16 + (lane & 15)) * 256 + (lane >> 4) * 16);
#pragma unroll
    for (int kc = 0; kc < 8; kc++) { LDA(ahi[kc], ao + kc * 32); LDA(alo[kc], ao + 32768 + kc * 32); }
    const unsigned bb = su32(sx) + 65536u + (unsigned)((lane & 15) * 528);

#pragma unroll 1
    for (int nc = 0; nc < 32; nc++) {
        float da[4] = {0,0,0,0}, db[4] = {0,0,0,0};
#pragma unroll
        for (int kc = 0; kc < 8; kc++) {
            unsigned b0, b1;
            LDB(b0, b1, bb + kc * 8448 + nc * 16);
            MMAH(da, ahi[kc], b0, b1);
            MMAH(db, alo[kc], b0, b1);
        }
        const int c = nc * 8 + (lane & 3) * 2, g = lane >> 2;
        float2 b2 = *(float2*)(bias + c);
        float2 o1 = make_float2(da[0] + db[0] + b2.x, da[1] + db[1] + b2.y);
        float2 o2 = make_float2(da[2] + db[2] + b2.x, da[3] + db[3] + b2.y);
        *(float2*)(g_gx + (size_t)(bt0 + w * 16 + g) * G4_ + col0 + c) = o1;
        *(float2*)(g_gx + (size_t)(bt0 + w * 16 + g + 8) * G4_ + col0 + c) = o2;
    }
}

// ---- k_lstm: R13 structure, single-plane fp16 W (1-term MMA) -----------------
// smem: bars@0; hT@1024 [2 buf][256 k][16 n] fp16 (16KB);
// gt@17408 [128][18]f; hs@26624 [2 buf][512] fp16 (2KB);
// Wst@28672 128x256 fp16 (64KB, init only); total 94208
#define LSMB 94208
__global__ void __launch_bounds__(256, 1) __cluster_dims__(CL_, 1, 1)
k_lstm(const float* __restrict__ W_hh, float* __restrict__ out_h) {
    extern __shared__ __align__(1024) char smc[];
    float* smf = (float*)smc;
    const int tid = threadIdx.x, wid = tid >> 5, lane = tid & 31;
    unsigned rank; asm("mov.u32 %0, %%cluster_ctarank;" : "=r"(rank));
    const int b0 = (blockIdx.x / CL_) * 16;
    const unsigned sb = su32(smc);

    if (tid == 0) {
        mbar_init(sb + 0, 8);  mbar_init(sb + 8, 8);    // full[0], full[1]
        mbar_init(sb + 16, 8); mbar_init(sb + 24, 8);   // empty[0], empty[1]
    }
    for (int i = tid; i < 4096; i += 256) smf[256 + i] = 0.f;   // zero hT

    // W A-fragments: single fp16 plane
    __half* Wst = (__half*)(smc + 28672);
    unsigned ahi[16][4];
    const unsigned abase = su32(Wst) + (unsigned)((wid * 16 + (lane & 15)) * 512 + (lane >> 4) * 16);
    for (int i = tid; i < 32768; i += 256) {
        int r = i >> 8, k = i & 255;
        int grow = (r >> 5) * H_ + (int)rank * 32 + (r & 31);
        Wst[r * 256 + k] = __float2half(W_hh[grow * H_ + k]);
    }
    __syncthreads();
#pragma unroll
    for (int kc = 0; kc < 16; kc++) LDA(ahi[kc], abase + kc * 32);
    __syncthreads();

    unsigned rbase[CL_];
#pragma unroll
    for (int pr = 0; pr < CL_; pr++) rbase[pr] = mapa_rank(sb, pr);

    const unsigned hT0 = sb + 1024;                       // buf stride 8192 B
    const unsigned brow = (unsigned)((lane & 15) * 32);

    const int jl = tid & 31, m0 = tid >> 5;
    float c0 = 0.f, c1 = 0.f;
    float* gt = (float*)(smc + 17408);
    __half* hs = (__half*)(smc + 26624);
    float* o0 = out_h + (size_t)(b0 + m0) * T_ * H_ + (int)rank * 32 + jl;
    float* o1 = out_h + (size_t)(b0 + m0 + 8) * T_ * H_ + (int)rank * 32 + jl;
    const float* gxb = g_gx + (size_t)b0 * T_ * G4_ + (int)rank * 32 + jl;

    const int wck = tid & 63;
    const int rg = (tid >> 6) * 2;
    const uint4* wsrc = (const uint4*)(smc + 26624 + wck * 16);
    const unsigned wdst = (unsigned)(1024 + (int)rank * 1024 + wck * 16);

    csync();

    for (int t = 0; t < T_; t++) {
        const int p = t & 1;
        const unsigned pw = (unsigned)(((t - 1) >> 1) & 1);

        const float* gp = gxb + (size_t)t * G4_;
        float gx[8];
#pragma unroll
        for (int q = 0; q < 4; q++) {
            gx[q]     = gp[(size_t)m0 * T_ * G4_ + q * 256];
            gx[4 + q] = gp[(size_t)(m0 + 8) * T_ * G4_ + q * 256];
        }

        float d0[4] = {0.f, 0.f, 0.f, 0.f}, d1[4] = {0.f, 0.f, 0.f, 0.f};
        if (t > 0) {
            if (wid == 0) mwait(sb + p * 8, pw);         // full[p]
            __syncthreads();
            const unsigned bbh = hT0 + (unsigned)p * 8192 + brow;
            float a0[4] = {0,0,0,0}, e0[4] = {0,0,0,0};
            float a1[4] = {0,0,0,0}, e1[4] = {0,0,0,0};
#pragma unroll
            for (int kc = 0; kc < 16; kc += 2) {
                unsigned bh0, bh1, ch0, ch1, dh0, dh1, eh0, eh1;
                LDB(bh0, bh1, bbh + kc * 512);
                LDB(ch0, ch1, bbh + kc * 512 + 16);
                LDB(dh0, dh1, bbh + (kc + 1) * 512);
                LDB(eh0, eh1, bbh + (kc + 1) * 512 + 16);
                MMAH(a0, ahi[kc], bh0, bh1);
                MMAH(a1, ahi[kc], ch0, ch1);
                MMAH(e0, ahi[kc + 1], dh0, dh1);
                MMAH(e1, ahi[kc + 1], eh0, eh1);
            }
#pragma unroll
            for (int i = 0; i < 4; i++) { d0[i] = a0[i] + e0[i]; d1[i] = a1[i] + e1[i]; }
        }
        {
            int g = lane >> 2, tt = (lane & 3) * 2;
            float* r0 = gt + (wid * 16 + g) * 18;
            float* r1 = r0 + 8 * 18;
            *(float2*)(r0 + tt) = make_float2(d0[0], d0[1]);
            *(float2*)(r1 + tt) = make_float2(d0[2], d0[3]);
            *(float2*)(r0 + 8 + tt) = make_float2(d1[0], d1[1]);
            *(float2*)(r1 + 8 + tt) = make_float2(d1[2], d1[3]);
        }
        __syncthreads();
        if (tid < 8) arr_remote(rbase[tid] + 16 + p * 8);   // release empty[p]

        float gi = gt[jl * 18 + m0] + gx[0];
        float gf = gt[(32 + jl) * 18 + m0] + gx[1];
        float gg = gt[(64 + jl) * 18 + m0] + gx[2];
        float go = gt[(96 + jl) * 18 + m0] + gx[3];
        c0 = sigm(gf) * c0 + sigm(gi) * ftanh(gg);
        float h0 = sigm(go) * ftanh(c0);
        gi = gt[jl * 18 + m0 + 8] + gx[4];
        gf = gt[(32 + jl) * 18 + m0 + 8] + gx[5];
        gg = gt[(64 + jl) * 18 + m0 + 8] + gx[6];
        go = gt[(96 + jl) * 18 + m0 + 8] + gx[7];
        c1 = sigm(gf) * c1 + sigm(gi) * ftanh(gg);
        float h1 = sigm(go) * ftanh(c1);

        o0[(size_t)t * H_] = h0;
        o1[(size_t)t * H_] = h1;

        if (t < T_ - 1) {
            const int q = p ^ 1;
            __half* hq = hs + q * 512;
            hq[jl * 16 + m0] = __float2half(h0);
            hq[jl * 16 + m0 + 8] = __float2half(h1);
            if (wid == 0 && t > 0) mwait(sb + 16 + q * 8, pw);   // empty[q]
            __syncthreads();
            uint4 v = *(const uint4*)((const char*)wsrc + q * 1024);
            unsigned drel = wdst + (unsigned)(q * 8192);
            st_cl_v4(rbase[rg] + drel, v);
            st_cl_v4(rbase[rg + 1] + drel, v);
            __syncthreads();
            if (tid < 8) arr_remote(rbase[tid] + q * 8);   // full[q] release
        }
    }
    csync();
}

// ---- launch -------------------------------------------------------------------
extern "C" void kernel_launch(void* const* d_in, const int* in_sizes, int n_in,
                              void* d_out, int out_size) {
    const float* input = (const float*)d_in[0];
    const float* W_ih  = (const float*)d_in[1];
    const float* W_hh  = (const float*)d_in[2];
    const float* b_ih  = (const float*)d_in[3];
    const float* b_hh  = (const float*)d_in[4];
    const float* fc_w  = (const float*)d_in[5];
    float* out   = (float*)d_out;
    float* out_w = out;
    float* out_h = out + (size_t)B_ * T_ * K_;

    cudaFuncSetAttribute(k_xgemm, cudaFuncAttributeMaxDynamicSharedMemorySize, XGB);
    cudaFuncSetAttribute(k_lstm,  cudaFuncAttributeMaxDynamicSharedMemorySize, LSMB);

    k_alpha<<<B_, 512>>>(input, fc_w, out_w);
    k_xgemm<<<(BT_ / 128) * 4, 256, XGB>>>(out_w, W_ih, b_ih, b_hh);
    k_lstm<<<(B_ / 16) * CL_, 256, LSMB>>>(W_hh, out_h);
}